// round 2
// baseline (speedup 1.0000x reference)
#include <cuda_runtime.h>

// Problem constants
#define N_   8
#define C_   64
#define H_   256
#define W_   256
#define HO_  256
#define WO_  256

// NHWC scratch for x (134.2 MB) — __device__ global, no allocation.
__device__ float g_xt[(size_t)N_ * H_ * W_ * C_];

// -------------------------------------------------------------------------
// Kernel 1: NCHW -> NHWC transpose. Per-n 2D transpose of [C=64] x [S=65536].
// 32x32 tiles in shared; both read and write fully coalesced.
// -------------------------------------------------------------------------
__global__ __launch_bounds__(256) void transpose_nchw_nhwc(const float* __restrict__ x) {
    __shared__ float tile[32][33];
    const int n  = blockIdx.z;
    const int s0 = blockIdx.x * 32;   // spatial (h*W + w)
    const int c0 = blockIdx.y * 32;   // channel
    const float* xin  = x    + (size_t)n * C_ * H_ * W_;
    float*       xout = g_xt + (size_t)n * H_ * W_ * C_;
    const int tx = threadIdx.x, ty = threadIdx.y;

    #pragma unroll
    for (int i = 0; i < 32; i += 8) {
        const int c = c0 + ty + i;
        const int s = s0 + tx;
        tile[ty + i][tx] = xin[(size_t)c * (H_ * W_) + s];
    }
    __syncthreads();
    #pragma unroll
    for (int i = 0; i < 32; i += 8) {
        const int s = s0 + ty + i;
        const int c = c0 + tx;
        xout[(size_t)s * C_ + c] = tile[tx][ty + i];
    }
}

// -------------------------------------------------------------------------
// Kernel 2: bilinear grid sample from NHWC scratch.
// Block = 256 threads (8 warps) handles 64 consecutive wo pixels of one
// (n, ho) row. Warp-per-pixel: each lane covers 2 channels via float2, so
// every corner fetch is a coalesced 256B read covering all 64 channels.
// Results staged in shared, then written to NCHW with coalesced 256B runs.
// -------------------------------------------------------------------------
__global__ __launch_bounds__(256) void grid_sample_kernel(
    const float* __restrict__ grid, float* __restrict__ out) {
    __shared__ float sm[64 * 65];   // [pixel][channel], stride 65 to dodge conflicts

    const int bid     = blockIdx.x;
    const int wo_base = (bid & 3) * 64;        // WO_/64 = 4 tiles per row
    const int ho      = (bid >> 2) & (HO_ - 1);
    const int n       = bid >> 10;             // 4*256 blocks per image

    const int tid  = threadIdx.x;
    const int warp = tid >> 5;
    const int lane = tid & 31;

    const float* gbase = grid + (((size_t)n * HO_ + ho) * WO_ + wo_base) * 2;
    const float* xt    = g_xt + (size_t)n * (H_ * W_ * C_);

    #pragma unroll
    for (int i = 0; i < 8; i++) {
        const int p = warp * 8 + i;            // pixel within tile (0..63)

        const float gx = gbase[p * 2 + 0];
        const float gy = gbase[p * 2 + 1];

        const float ix = (gx + 1.0f) * 0.5f * (float)(W_ - 1);
        const float iy = (gy + 1.0f) * 0.5f * (float)(H_ - 1);

        const float x0f = floorf(ix);
        const float y0f = floorf(iy);
        const float wx1 = ix - x0f;
        const float wy1 = iy - y0f;
        const float wx0 = 1.0f - wx1;
        const float wy0 = 1.0f - wy1;

        const int xi = (int)x0f;
        const int yi = (int)y0f;
        const int x0 = min(max(xi,     0), W_ - 1);
        const int x1 = min(max(xi + 1, 0), W_ - 1);
        const int y0 = min(max(yi,     0), H_ - 1);
        const int y1 = min(max(yi + 1, 0), H_ - 1);

        const float w00 = wy0 * wx0;
        const float w01 = wy0 * wx1;
        const float w10 = wy1 * wx0;
        const float w11 = wy1 * wx1;

        const float2* p00 = (const float2*)(xt + ((size_t)(y0 * W_ + x0) * C_)) + lane;
        const float2* p01 = (const float2*)(xt + ((size_t)(y0 * W_ + x1) * C_)) + lane;
        const float2* p10 = (const float2*)(xt + ((size_t)(y1 * W_ + x0) * C_)) + lane;
        const float2* p11 = (const float2*)(xt + ((size_t)(y1 * W_ + x1) * C_)) + lane;

        const float2 v00 = *p00;
        const float2 v01 = *p01;
        const float2 v10 = *p10;
        const float2 v11 = *p11;

        float2 r;
        r.x = w00 * v00.x + w01 * v01.x + w10 * v10.x + w11 * v11.x;
        r.y = w00 * v00.y + w01 * v01.y + w10 * v10.y + w11 * v11.y;

        const int c2 = lane * 2;
        sm[p * 65 + c2]     = r.x;
        sm[p * 65 + c2 + 1] = r.y;
    }
    __syncthreads();

    // Write NCHW: for each channel, 64 consecutive wo -> coalesced 256B stores.
    float* obase = out + (size_t)n * (C_ * HO_ * WO_) + (size_t)ho * WO_ + wo_base;
    #pragma unroll
    for (int it = 0; it < 16; it++) {
        const int j = tid & 63;
        const int c = (tid >> 6) + it * 4;
        obase[(size_t)c * (HO_ * WO_) + j] = sm[j * 65 + c];
    }
}

extern "C" void kernel_launch(void* const* d_in, const int* in_sizes, int n_in,
                              void* d_out, int out_size) {
    const float* x    = (const float*)d_in[0];   // [N, C, H, W]
    const float* grid = (const float*)d_in[1];   // [N, HO, WO, 2]
    float* out        = (float*)d_out;           // [N, C, HO, WO]
    (void)in_sizes; (void)n_in; (void)out_size;

    // Kernel 1: NCHW -> NHWC
    dim3 tgrid(H_ * W_ / 32, C_ / 32, N_);   // (2048, 2, 8)
    dim3 tblock(32, 8);
    transpose_nchw_nhwc<<<tgrid, tblock>>>(x);

    // Kernel 2: gather + bilinear blend + NCHW store
    const int nblocks = N_ * HO_ * (WO_ / 64);   // 8192
    grid_sample_kernel<<<nblocks, 256>>>(grid, out);
}

// round 3
// speedup vs baseline: 1.0568x; 1.0568x over previous
#include <cuda_runtime.h>
#include <cuda_fp16.h>

// Problem constants
#define N_   8
#define C_   64
#define H_   256
#define W_   256
#define HO_  256
#define WO_  256

// NHWC scratch for x in fp16 (67 MB) — __device__ global, no allocation.
__device__ __half g_xt[(size_t)N_ * H_ * W_ * C_];

// -------------------------------------------------------------------------
// Kernel 1: NCHW fp32 -> NHWC fp16.
// Block = 256 threads handles 64 consecutive spatial pixels x all 64 channels.
// Reads: 64 channel-rows of 256B (coalesced). Writes: one contiguous 8KB run
// of halves (fully coalesced, 8B per thread-store).
// -------------------------------------------------------------------------
__global__ __launch_bounds__(256) void nchw_to_nhwc_h(const float* __restrict__ x) {
    // stride 68 halves = 136B: 8B-aligned rows, modest bank conflicts
    __shared__ __half smh[64][68];

    const int n  = blockIdx.y;
    const int s0 = blockIdx.x * 64;
    const float* xin = x + (size_t)n * (C_ * H_ * W_);
    const int tid   = threadIdx.x;
    const int j     = tid & 63;     // pixel within tile
    const int cbase = tid >> 6;     // 0..3

    #pragma unroll
    for (int it = 0; it < 16; it++) {
        const int c = it * 4 + cbase;
        smh[j][c] = __float2half_rn(xin[(size_t)c * (H_ * W_) + s0 + j]);
    }
    __syncthreads();

    // Write 64*64 halves contiguously: half index k in [0,4096),
    // pixel = k>>6, channel = k&63. Thread covers k = tid*16 .. tid*16+15.
    uint2* ob = (uint2*)(g_xt + ((size_t)n * (H_ * W_) + s0) * C_);
    const int p  = tid >> 2;         // pixel 0..63
    const int c0 = (tid & 3) * 16;   // 0,16,32,48
    #pragma unroll
    for (int i = 0; i < 4; i++) {
        const uint2 v = *(const uint2*)(&smh[p][c0 + i * 4]);  // 4 halves, 8B aligned
        ob[tid * 4 + i] = v;
    }
}

// -------------------------------------------------------------------------
// Kernel 2: bilinear grid sample from NHWC fp16 scratch.
// Block = 256 threads (8 warps) handles 64 consecutive wo pixels of one
// (n, ho) row. Warp-per-pixel: each lane covers 2 channels via half2, so
// every corner fetch is a coalesced 128B read covering all 64 channels.
// Blend in fp32; stage results in shared; write NCHW in coalesced 256B runs.
// -------------------------------------------------------------------------
__global__ __launch_bounds__(256) void grid_sample_kernel(
    const float* __restrict__ grid, float* __restrict__ out) {
    __shared__ float sm[64 * 65];   // [pixel][channel], stride 65

    const int bid     = blockIdx.x;
    const int wo_base = (bid & 3) * 64;
    const int ho      = (bid >> 2) & (HO_ - 1);
    const int n       = bid >> 10;

    const int tid  = threadIdx.x;
    const int warp = tid >> 5;
    const int lane = tid & 31;

    const float* gbase = grid + (((size_t)n * HO_ + ho) * WO_ + wo_base) * 2;
    const __half* xt   = g_xt + (size_t)n * (H_ * W_ * C_);

    #pragma unroll
    for (int i = 0; i < 8; i++) {
        const int p = warp * 8 + i;

        const float gx = gbase[p * 2 + 0];
        const float gy = gbase[p * 2 + 1];

        const float ix = (gx + 1.0f) * 0.5f * (float)(W_ - 1);
        const float iy = (gy + 1.0f) * 0.5f * (float)(H_ - 1);

        const float x0f = floorf(ix);
        const float y0f = floorf(iy);
        const float wx1 = ix - x0f;
        const float wy1 = iy - y0f;
        const float wx0 = 1.0f - wx1;
        const float wy0 = 1.0f - wy1;

        const int xi = (int)x0f;
        const int yi = (int)y0f;
        const int x0 = min(max(xi,     0), W_ - 1);
        const int x1 = min(max(xi + 1, 0), W_ - 1);
        const int y0 = min(max(yi,     0), H_ - 1);
        const int y1 = min(max(yi + 1, 0), H_ - 1);

        const float w00 = wy0 * wx0;
        const float w01 = wy0 * wx1;
        const float w10 = wy1 * wx0;
        const float w11 = wy1 * wx1;

        const __half2* p00 = (const __half2*)(xt + (size_t)(y0 * W_ + x0) * C_) + lane;
        const __half2* p01 = (const __half2*)(xt + (size_t)(y0 * W_ + x1) * C_) + lane;
        const __half2* p10 = (const __half2*)(xt + (size_t)(y1 * W_ + x0) * C_) + lane;
        const __half2* p11 = (const __half2*)(xt + (size_t)(y1 * W_ + x1) * C_) + lane;

        const float2 v00 = __half22float2(*p00);
        const float2 v01 = __half22float2(*p01);
        const float2 v10 = __half22float2(*p10);
        const float2 v11 = __half22float2(*p11);

        float2 r;
        r.x = w00 * v00.x + w01 * v01.x + w10 * v10.x + w11 * v11.x;
        r.y = w00 * v00.y + w01 * v01.y + w10 * v10.y + w11 * v11.y;

        const int c2 = lane * 2;
        sm[p * 65 + c2]     = r.x;
        sm[p * 65 + c2 + 1] = r.y;
    }
    __syncthreads();

    // Write NCHW: for each channel, 64 consecutive wo -> coalesced 256B stores.
    float* obase = out + (size_t)n * (C_ * HO_ * WO_) + (size_t)ho * WO_ + wo_base;
    #pragma unroll
    for (int it = 0; it < 16; it++) {
        const int j = tid & 63;
        const int c = (tid >> 6) + it * 4;
        obase[(size_t)c * (HO_ * WO_) + j] = sm[j * 65 + c];
    }
}

extern "C" void kernel_launch(void* const* d_in, const int* in_sizes, int n_in,
                              void* d_out, int out_size) {
    const float* x    = (const float*)d_in[0];   // [N, C, H, W]
    const float* grid = (const float*)d_in[1];   // [N, HO, WO, 2]
    float* out        = (float*)d_out;           // [N, C, HO, WO]
    (void)in_sizes; (void)n_in; (void)out_size;

    // Kernel 1: NCHW fp32 -> NHWC fp16
    dim3 tgrid(H_ * W_ / 64, N_);   // (1024, 8)
    nchw_to_nhwc_h<<<tgrid, 256>>>(x);

    // Kernel 2: gather + bilinear blend + NCHW store
    const int nblocks = N_ * HO_ * (WO_ / 64);   // 8192
    grid_sample_kernel<<<nblocks, 256>>>(grid, out);
}